// round 16
// baseline (speedup 1.0000x reference)
#include <cuda_runtime.h>
#include <cstdint>

#define FULLMASK 0xffffffffu
#define NT 32
#define NB 64
#define ND 512
#define NH 512
#define NP 64

__device__ __forceinline__ float2 mk2(float a, float b) { float2 r; r.x = a; r.y = b; return r; }

__device__ __forceinline__ float2 f2fma(float2 a, float2 b, float2 c) {
    float2 d;
    asm("fma.rn.f32x2 %0, %1, %2, %3;"
        : "=l"(reinterpret_cast<unsigned long long&>(d))
        : "l"(reinterpret_cast<unsigned long long&>(a)),
          "l"(reinterpret_cast<unsigned long long&>(b)),
          "l"(reinterpret_cast<unsigned long long&>(c)));
    return d;
}
__device__ __forceinline__ float2 f2mul(float2 a, float2 b) {
    float2 d;
    asm("mul.rn.f32x2 %0, %1, %2;"
        : "=l"(reinterpret_cast<unsigned long long&>(d))
        : "l"(reinterpret_cast<unsigned long long&>(a)),
          "l"(reinterpret_cast<unsigned long long&>(b)));
    return d;
}

// ---------------------------------------------------------------------------
// One 8-qubit circuit, warp-resident, f32x2-packed, pre-splatted U (R10 layout).
// ang[8] in/out (updated with <Z_0..7>). Final CNOT folded into measurement.
// ---------------------------------------------------------------------------
__device__ __forceinline__ void run_circuit(const float* __restrict__ L,
                                            float ang[8], int lane) {
    float cq[8], sq[8];
    #pragma unroll
    for (int q = 0; q < 8; q++) __sincosf(0.5f * ang[q], &sq[q], &cq[q]);

    float ml = 1.f;
    #pragma unroll
    for (int p = 0; p < 5; p++) ml *= (lane >> p & 1) ? sq[7 - p] : cq[7 - p];
    int pl = __popc(lane);
    float sre[8], sim[8];
    #pragma unroll
    for (int r = 0; r < 8; r++) {
        float m = ml;
        #pragma unroll
        for (int j = 0; j < 3; j++) m *= (r >> j & 1) ? sq[2 - j] : cq[2 - j];
        int pop = (pl + __popc(r)) & 3;
        sre[r] = (pop == 0) ? m : ((pop == 2) ? -m : 0.f);
        sim[r] = (pop == 1) ? -m : ((pop == 3) ? m : 0.f);
    }
    float2 RE[4], IM[4];
    #pragma unroll
    for (int j = 0; j < 4; j++) { RE[j] = mk2(sre[j], sre[j + 4]); IM[j] = mk2(sim[j], sim[j + 4]); }

    #pragma unroll
    for (int d = 0; d < 2; d++) {
        const float* Ld = L + d * 192;
        {   // qubit 0 (pack dim): half-swap gate
            const float2* c = reinterpret_cast<const float2*>(Ld);
            float2 c0r = c[0], c0i = c[1], c0in = c[2];
            float2 c1r = c[3], c1i = c[4], c1in = c[5];
            #pragma unroll
            for (int j = 0; j < 4; j++) {
                float2 Ro = RE[j], Io = IM[j];
                float2 Rs = mk2(Ro.y, Ro.x), Is = mk2(Io.y, Io.x);
                RE[j] = f2fma(Is, c1in, f2fma(Rs, c1r, f2fma(Io, c0in, f2mul(Ro, c0r))));
                IM[j] = f2fma(Rs, c1i,  f2fma(Is, c1r, f2fma(Ro, c0i,  f2mul(Io, c0r))));
            }
        }
        #pragma unroll
        for (int w = 1; w < 3; w++) {
            const float2* c = reinterpret_cast<const float2*>(Ld + w * 24);
            float2 s00r = c[0], s00i = c[1], s00in = c[2];
            float2 s01r = c[3], s01i = c[4], s01in = c[5];
            float2 s10r = c[6], s10i = c[7], s10in = c[8];
            float2 s11r = c[9], s11i = c[10], s11in = c[11];
            int m = (w == 1) ? 2 : 1;
            #pragma unroll
            for (int j = 0; j < 4; j++) {
                if (j & m) continue;
                int j1 = j | m;
                float2 a0R = RE[j], a0I = IM[j], a1R = RE[j1], a1I = IM[j1];
                RE[j]  = f2fma(a1I, s01in, f2fma(a1R, s01r, f2fma(a0I, s00in, f2mul(a0R, s00r))));
                IM[j]  = f2fma(a1R, s01i,  f2fma(a1I, s01r, f2fma(a0R, s00i,  f2mul(a0I, s00r))));
                RE[j1] = f2fma(a1I, s11in, f2fma(a1R, s11r, f2fma(a0I, s10in, f2mul(a0R, s10r))));
                IM[j1] = f2fma(a1R, s11i,  f2fma(a1I, s11r, f2fma(a0R, s10i,  f2mul(a0I, s10r))));
            }
        }
        #pragma unroll
        for (int w = 3; w < 8; w++) {
            int lm = 1 << (7 - w);
            const float2* c = reinterpret_cast<const float2*>(
                Ld + w * 24 + ((lane & lm) ? 12 : 0));
            float2 sar = c[0], sai = c[1], sain = c[2];
            float2 sbr = c[3], sbi = c[4], sbin = c[5];
            #pragma unroll
            for (int j = 0; j < 4; j++) {
                float2 P, Q;
                P.x = __shfl_xor_sync(FULLMASK, RE[j].x, lm);
                P.y = __shfl_xor_sync(FULLMASK, RE[j].y, lm);
                Q.x = __shfl_xor_sync(FULLMASK, IM[j].x, lm);
                Q.y = __shfl_xor_sync(FULLMASK, IM[j].y, lm);
                float2 Ro = RE[j], Io = IM[j];
                RE[j] = f2fma(Q, sbin, f2fma(P, sbr, f2fma(Io, sain, f2mul(Ro, sar))));
                IM[j] = f2fma(P, sbi,  f2fma(Q, sbr, f2fma(Ro, sai,  f2mul(Io, sar))));
            }
        }
        if (d == 0) {
            int g0 = lane ^ (lane >> 1);
            float2 nR[4], nI[4];
            #pragma unroll
            for (int j = 0; j < 4; j++) {
                int sl = g0 ^ ((j & 1) << 4);
                int sA = j ^ (j >> 1), sB = sA ^ 2;
                nR[j].x = __shfl_sync(FULLMASK, RE[sA].x, sl);
                nR[j].y = __shfl_sync(FULLMASK, RE[sB].y, sl);
                nI[j].x = __shfl_sync(FULLMASK, IM[sA].x, sl);
                nI[j].y = __shfl_sync(FULLMASK, IM[sB].y, sl);
            }
            #pragma unroll
            for (int j = 0; j < 4; j++) { RE[j] = nR[j]; IM[j] = nI[j]; }
        }
    }

    float px[4], py[4];
    #pragma unroll
    for (int j = 0; j < 4; j++) {
        float2 p2 = f2fma(IM[j], IM[j], f2mul(RE[j], RE[j]));
        px[j] = p2.x; py[j] = p2.y;
    }
    float C = (px[0] + px[1] + px[2] + px[3]) - (py[0] + py[1] + py[2] + py[3]);
    float B = (px[0] + px[1] - px[2] - px[3]) - (py[0] + py[1] - py[2] - py[3]);
    float A = (px[0] - px[1] - px[2] + px[3]) - (py[0] - py[1] - py[2] + py[3]);
    float v[8];
    v[0] = C;
    v[1] = B;
    v[2] = A;
    v[3] = (lane & 16)              ? -A : A;
    v[4] = (__popc(lane >> 3) & 1)  ? -A : A;
    v[5] = (__popc(lane >> 2) & 1)  ? -A : A;
    v[6] = (__popc(lane >> 1) & 1)  ? -A : A;
    v[7] = (__popc(lane) & 1)       ? -A : A;
    #pragma unroll
    for (int off = 16; off; off >>= 1) {
        #pragma unroll
        for (int q = 0; q < 8; q++)
            v[q] += __shfl_xor_sync(FULLMASK, v[q], off);
    }
    #pragma unroll
    for (int q = 0; q < 8; q++) ang[q] = v[q];
}

__device__ __forceinline__ float fast_sigmoid(float x) { return 1.f / (1.f + __expf(-x)); }
__device__ __forceinline__ float fast_tanh(float x)    { return 2.f / (1.f + __expf(-2.f * x)) - 1.f; }

// ---------------------------------------------------------------------------
// SINGLE kernel. One CTA per batch element, 8 warps.
// Prologue (per CTA, redundant but cheap — all weight data L1/L2 cached):
//   warp w: Mx[w] into 16 regs -> xsq[t][w] for all 32 steps -> Mh[w] regs.
// Main loop (unchanged from R15): qs[w] = hx . Mh[w]; circuits on warps 0-3;
// output stage on all warps. 3 barriers/step.
// ---------------------------------------------------------------------------
__global__ __launch_bounds__(256, 1)
void qlstm_main(const float* __restrict__ inputs,
                const float* __restrict__ W_proj,
                const float* __restrict__ b_proj,
                const float* __restrict__ W_toq,
                const float* __restrict__ W_q2h,
                const float* __restrict__ fpar, const float* __restrict__ ipar,
                const float* __restrict__ gpar, const float* __restrict__ opar,
                float* __restrict__ out) {
    __shared__ float wq[NH * 9];
    __shared__ float wtoq[8 * 64];
    __shared__ __align__(16) float Usm[8 * 384];
    __shared__ __align__(16) float hx[NH];
    __shared__ float xsq[NT * 8];
    __shared__ float qs[8];
    __shared__ float ybuf[32];

    int tid = threadIdx.x, lane = tid & 31, wid = tid >> 5;
    int bb = blockIdx.x;

    for (int idx = tid; idx < NH * 8; idx += 256)
        wq[(idx >> 3) * 9 + (idx & 7)] = W_q2h[idx];
    for (int idx = tid; idx < 512; idx += 256) wtoq[idx] = W_toq[idx];
    for (int idx = tid; idx < 512; idx += 256) hx[idx] = 0.f;

    if (tid < 128) {
        int q = tid & 7, d = (tid >> 3) & 1, gc = (tid >> 4) & 1, gi = tid >> 5;
        const float* P = (gi == 0) ? fpar : (gi == 1) ? ipar : (gi == 2) ? gpar : opar;
        const float* pp = P + ((gc * 2 + d) * 8 + q) * 3;
        float a = 0.5f * pp[0], b = 0.5f * pp[1], c = 0.5f * pp[2];
        float ca = cosf(a), sa = sinf(a);
        float cb = cosf(b), sb = sinf(b);
        float cc = cosf(c), sc = sinf(c);
        float m00r =  ca * cb, m00i = -ca * sb;
        float m01r = -sa * cb, m01i =  sa * sb;
        float m10r =  sa * cb, m10i =  sa * sb;
        float m11r =  ca * cb, m11i =  ca * sb;
        float u00r =  cc * m00r + sc * m10i, u00i =  cc * m00i - sc * m10r;
        float u01r =  cc * m01r + sc * m11i, u01i =  cc * m01i - sc * m11r;
        float u10r =  sc * m00i + cc * m10r, u10i = -sc * m00r + cc * m10i;
        float u11r =  sc * m01i + cc * m11r, u11i = -sc * m01r + cc * m11i;

        float* L = Usm + ((gi * 2 + gc) * 2 + d) * 192 + q * 24;
        if (q == 0) {
            L[0]  = u00r;  L[1]  = u11r;
            L[2]  = u00i;  L[3]  = u11i;
            L[4]  = -u00i; L[5]  = -u11i;
            L[6]  = u01r;  L[7]  = u10r;
            L[8]  = u01i;  L[9]  = u10i;
            L[10] = -u01i; L[11] = -u10i;
        } else if (q < 3) {
            L[0]=u00r;  L[1]=u00r;   L[2]=u00i;  L[3]=u00i;   L[4]=-u00i; L[5]=-u00i;
            L[6]=u01r;  L[7]=u01r;   L[8]=u01i;  L[9]=u01i;   L[10]=-u01i;L[11]=-u01i;
            L[12]=u10r; L[13]=u10r;  L[14]=u10i; L[15]=u10i;  L[16]=-u10i;L[17]=-u10i;
            L[18]=u11r; L[19]=u11r;  L[20]=u11i; L[21]=u11i;  L[22]=-u11i;L[23]=-u11i;
        } else {
            L[0]=u00r;  L[1]=u00r;   L[2]=u00i;  L[3]=u00i;   L[4]=-u00i; L[5]=-u00i;
            L[6]=u01r;  L[7]=u01r;   L[8]=u01i;  L[9]=u01i;   L[10]=-u01i;L[11]=-u01i;
            L[12]=u11r; L[13]=u11r;  L[14]=u11i; L[15]=u11i;  L[16]=-u11i;L[17]=-u11i;
            L[18]=u10r; L[19]=u10r;  L[20]=u10i; L[21]=u10i;  L[22]=-u10i;L[23]=-u10i;
        }
    }
    __syncthreads();

    float mreg[16];
    {
        // --- Prologue A: Mx row for this warp (x-half of fused M) ---
        const float* wt = wtoq + wid * 64;
        #pragma unroll
        for (int i = 0; i < 16; i++) {
            float acc = 0.f;
            #pragma unroll 8
            for (int p = 0; p < 64; p++)
                acc = fmaf(wt[p], W_proj[p * 1024 + lane + 32 * i], acc);
            mreg[i] = acc;
        }
        // bq for this warp
        float bqv = 0.f;
        #pragma unroll
        for (int p = 0; p < 64; p++) bqv = fmaf(wt[p], b_proj[p], bqv);

        // --- Prologue B: xsq[t][wid] = bq + x_t . Mx[wid] for all 32 steps ---
        #pragma unroll 1
        for (int t = 0; t < NT; t++) {
            const float* xrow = inputs + (t * NB + bb) * ND;
            float acc = 0.f;
            #pragma unroll
            for (int i = 0; i < 16; i++)
                acc = fmaf(xrow[lane + 32 * i], mreg[i], acc);
            #pragma unroll
            for (int off = 16; off; off >>= 1)
                acc += __shfl_xor_sync(FULLMASK, acc, off);
            if (lane == 0) xsq[t * 8 + wid] = acc + bqv;
        }

        // --- Prologue C: Mh row (h-half) into the same registers ---
        #pragma unroll
        for (int i = 0; i < 16; i++) {
            float acc = 0.f;
            #pragma unroll 8
            for (int p = 0; p < 64; p++)
                acc = fmaf(wt[p], W_proj[p * 1024 + 512 + lane + 32 * i], acc);
            mreg[i] = acc;
        }
    }
    float cx0 = 0.f, cx1 = 0.f;
    __syncthreads();

    #pragma unroll 1
    for (int t = 0; t < NT; t++) {
        // --- qin dot: warp w computes hx . Mh[w] ---
        {
            float acc = 0.f;
            #pragma unroll
            for (int i = 0; i < 16; i++)
                acc = fmaf(hx[lane + 32 * i], mreg[i], acc);
            #pragma unroll
            for (int off = 16; off; off >>= 1)
                acc += __shfl_xor_sync(FULLMASK, acc, off);
            if (lane == 0) qs[wid] = acc;
        }
        __syncthreads();

        // --- quantum gates: warp w = gate w ---
        if (wid < 4) {
            float ang[8];
            #pragma unroll
            for (int j = 0; j < 8; j++) ang[j] = qs[j] + xsq[t * 8 + j];

            #pragma unroll 1
            for (int gc = 0; gc < 2; gc++)
                run_circuit(Usm + (wid * 2 + gc) * 384, ang, lane);

            if (lane == 0) {
                #pragma unroll
                for (int j = 0; j < 8; j++) ybuf[wid * 8 + j] = ang[j];
            }
        }
        __syncthreads();

        // --- output stage: y @ W_q2h.T, activations, LSTM cell update ---
        #pragma unroll
        for (int u = 0; u < 2; u++) {
            int h = tid + u * 256;
            float af = 0.f, aiv = 0.f, agv = 0.f, aov = 0.f;
            #pragma unroll
            for (int j = 0; j < 8; j++) {
                float w = wq[h * 9 + j];
                af  = fmaf(ybuf[j],      w, af);
                aiv = fmaf(ybuf[8 + j],  w, aiv);
                agv = fmaf(ybuf[16 + j], w, agv);
                aov = fmaf(ybuf[24 + j], w, aov);
            }
            float fv = fast_sigmoid(af);
            float iv = fast_sigmoid(aiv);
            float gv = fast_tanh(agv);
            float ov = fast_sigmoid(aov);
            float cprev = u ? cx1 : cx0;
            float cn = fv * cprev + iv * gv;
            if (u) cx1 = cn; else cx0 = cn;
            float hn = ov * fast_tanh(cn);
            hx[h] = hn;
            out[(t * NB + bb) * NH + h] = hn;
        }
        __syncthreads();
    }

    #pragma unroll
    for (int u = 0; u < 2; u++) {
        int h = tid + u * 256;
        out[NT * NB * NH + bb * NH + h]           = hx[h];
        out[NT * NB * NH + NB * NH + bb * NH + h] = (u ? cx1 : cx0);
    }
}

// ---------------------------------------------------------------------------
extern "C" void kernel_launch(void* const* d_in, const int* in_sizes, int n_in,
                              void* d_out, int out_size) {
    const float* inputs = (const float*)d_in[0];
    const float* W_proj = (const float*)d_in[1];
    const float* b_proj = (const float*)d_in[2];
    const float* W_toq  = (const float*)d_in[3];
    const float* W_q2h  = (const float*)d_in[4];
    const float* fp     = (const float*)d_in[5];
    const float* ip     = (const float*)d_in[6];
    const float* gp     = (const float*)d_in[7];
    const float* op     = (const float*)d_in[8];
    float* out = (float*)d_out;

    qlstm_main<<<NB, 256>>>(inputs, W_proj, b_proj, W_toq, W_q2h,
                            fp, ip, gp, op, out);
}

// round 17
// speedup vs baseline: 1.3584x; 1.3584x over previous
#include <cuda_runtime.h>
#include <cstdint>

#define FULLMASK 0xffffffffu
#define NT 32
#define NB 64
#define ND 512
#define NH 512
#define NP 64

__device__ float g_M[8 * 1024];        // M = W_toq @ W_proj  (8 x 1024)
__device__ float g_bq[8];              // bq = W_toq @ b_proj
__device__ float g_qinx[NT * NB * 8];  // qin x-part per (t,b,q)

__device__ __forceinline__ float2 mk2(float a, float b) { float2 r; r.x = a; r.y = b; return r; }

__device__ __forceinline__ float2 f2fma(float2 a, float2 b, float2 c) {
    float2 d;
    asm("fma.rn.f32x2 %0, %1, %2, %3;"
        : "=l"(reinterpret_cast<unsigned long long&>(d))
        : "l"(reinterpret_cast<unsigned long long&>(a)),
          "l"(reinterpret_cast<unsigned long long&>(b)),
          "l"(reinterpret_cast<unsigned long long&>(c)));
    return d;
}
__device__ __forceinline__ float2 f2mul(float2 a, float2 b) {
    float2 d;
    asm("mul.rn.f32x2 %0, %1, %2;"
        : "=l"(reinterpret_cast<unsigned long long&>(d))
        : "l"(reinterpret_cast<unsigned long long&>(a)),
          "l"(reinterpret_cast<unsigned long long&>(b)));
    return d;
}

// ---------------------------------------------------------------------------
// Kernel 1: M[q][k] = sum_p W_toq[q][p] * W_proj[p][k], 32 blocks (q x 4 chunks)
// ---------------------------------------------------------------------------
__global__ __launch_bounds__(256, 1)
void mprep_kernel(const float* __restrict__ W_proj,
                  const float* __restrict__ W_toq,
                  const float* __restrict__ b_proj) {
    __shared__ float wt[64];
    int q = blockIdx.x, chunk = blockIdx.y, tid = threadIdx.x;
    if (tid < 64) wt[tid] = W_toq[q * 64 + tid];
    __syncthreads();
    int k = chunk * 256 + tid;
    float acc = 0.f;
    #pragma unroll
    for (int p = 0; p < 64; p++)
        acc = fmaf(wt[p], W_proj[p * 1024 + k], acc);
    g_M[q * 1024 + k] = acc;
    if (chunk == 0 && tid == 0) {
        float b = 0.f;
        #pragma unroll
        for (int p = 0; p < 64; p++)
            b = fmaf(wt[p], b_proj[p], b);
        g_bq[q] = b;
    }
}

// ---------------------------------------------------------------------------
// Kernel 2: qinx[(t*64+b)][q] = bq[q] + x_row . M[q][0:512]
// 128 blocks x 16 rows; warp w owns q=w for all 16 rows.
// ---------------------------------------------------------------------------
__global__ __launch_bounds__(256, 1)
void qinx_kernel(const float* __restrict__ inputs) {
    __shared__ __align__(16) float xsm[16 * ND];
    int tid = threadIdx.x, lane = tid & 31, wid = tid >> 5;
    int blk = blockIdx.x;

    float mreg[16];
    #pragma unroll
    for (int i = 0; i < 16; i++) mreg[i] = g_M[wid * 1024 + lane + 32 * i];
    float bqv = g_bq[wid];

    for (int i = tid; i < 16 * ND; i += 256) xsm[i] = inputs[blk * (16 * ND) + i];
    __syncthreads();

    #pragma unroll 1
    for (int row = 0; row < 16; row++) {
        float acc = 0.f;
        #pragma unroll
        for (int i = 0; i < 16; i++)
            acc = fmaf(xsm[row * ND + lane + 32 * i], mreg[i], acc);
        #pragma unroll
        for (int off = 16; off; off >>= 1)
            acc += __shfl_xor_sync(FULLMASK, acc, off);
        if (lane == 0) g_qinx[(blk * 16 + row) * 8 + wid] = acc + bqv;
    }
}

// ---------------------------------------------------------------------------
// One 8-qubit circuit, warp-resident, f32x2-packed, pre-splatted U (R10 layout).
// ang[8] in/out (updated with <Z_0..7>). Final CNOT folded into measurement.
// ---------------------------------------------------------------------------
__device__ __forceinline__ void run_circuit(const float* __restrict__ L,
                                            float ang[8], int lane) {
    float cq[8], sq[8];
    #pragma unroll
    for (int q = 0; q < 8; q++) __sincosf(0.5f * ang[q], &sq[q], &cq[q]);

    float ml = 1.f;
    #pragma unroll
    for (int p = 0; p < 5; p++) ml *= (lane >> p & 1) ? sq[7 - p] : cq[7 - p];
    int pl = __popc(lane);
    float sre[8], sim[8];
    #pragma unroll
    for (int r = 0; r < 8; r++) {
        float m = ml;
        #pragma unroll
        for (int j = 0; j < 3; j++) m *= (r >> j & 1) ? sq[2 - j] : cq[2 - j];
        int pop = (pl + __popc(r)) & 3;
        sre[r] = (pop == 0) ? m : ((pop == 2) ? -m : 0.f);
        sim[r] = (pop == 1) ? -m : ((pop == 3) ? m : 0.f);
    }
    float2 RE[4], IM[4];
    #pragma unroll
    for (int j = 0; j < 4; j++) { RE[j] = mk2(sre[j], sre[j + 4]); IM[j] = mk2(sim[j], sim[j + 4]); }

    #pragma unroll
    for (int d = 0; d < 2; d++) {
        const float* Ld = L + d * 192;
        {   // qubit 0 (pack dim): half-swap gate
            const float2* c = reinterpret_cast<const float2*>(Ld);
            float2 c0r = c[0], c0i = c[1], c0in = c[2];
            float2 c1r = c[3], c1i = c[4], c1in = c[5];
            #pragma unroll
            for (int j = 0; j < 4; j++) {
                float2 Ro = RE[j], Io = IM[j];
                float2 Rs = mk2(Ro.y, Ro.x), Is = mk2(Io.y, Io.x);
                RE[j] = f2fma(Is, c1in, f2fma(Rs, c1r, f2fma(Io, c0in, f2mul(Ro, c0r))));
                IM[j] = f2fma(Rs, c1i,  f2fma(Is, c1r, f2fma(Ro, c0i,  f2mul(Io, c0r))));
            }
        }
        #pragma unroll
        for (int w = 1; w < 3; w++) {
            const float2* c = reinterpret_cast<const float2*>(Ld + w * 24);
            float2 s00r = c[0], s00i = c[1], s00in = c[2];
            float2 s01r = c[3], s01i = c[4], s01in = c[5];
            float2 s10r = c[6], s10i = c[7], s10in = c[8];
            float2 s11r = c[9], s11i = c[10], s11in = c[11];
            int m = (w == 1) ? 2 : 1;
            #pragma unroll
            for (int j = 0; j < 4; j++) {
                if (j & m) continue;
                int j1 = j | m;
                float2 a0R = RE[j], a0I = IM[j], a1R = RE[j1], a1I = IM[j1];
                RE[j]  = f2fma(a1I, s01in, f2fma(a1R, s01r, f2fma(a0I, s00in, f2mul(a0R, s00r))));
                IM[j]  = f2fma(a1R, s01i,  f2fma(a1I, s01r, f2fma(a0R, s00i,  f2mul(a0I, s00r))));
                RE[j1] = f2fma(a1I, s11in, f2fma(a1R, s11r, f2fma(a0I, s10in, f2mul(a0R, s10r))));
                IM[j1] = f2fma(a1R, s11i,  f2fma(a1I, s11r, f2fma(a0R, s10i,  f2mul(a0I, s10r))));
            }
        }
        #pragma unroll
        for (int w = 3; w < 8; w++) {
            int lm = 1 << (7 - w);
            const float2* c = reinterpret_cast<const float2*>(
                Ld + w * 24 + ((lane & lm) ? 12 : 0));
            float2 sar = c[0], sai = c[1], sain = c[2];
            float2 sbr = c[3], sbi = c[4], sbin = c[5];
            #pragma unroll
            for (int j = 0; j < 4; j++) {
                float2 P, Q;
                P.x = __shfl_xor_sync(FULLMASK, RE[j].x, lm);
                P.y = __shfl_xor_sync(FULLMASK, RE[j].y, lm);
                Q.x = __shfl_xor_sync(FULLMASK, IM[j].x, lm);
                Q.y = __shfl_xor_sync(FULLMASK, IM[j].y, lm);
                float2 Ro = RE[j], Io = IM[j];
                RE[j] = f2fma(Q, sbin, f2fma(P, sbr, f2fma(Io, sain, f2mul(Ro, sar))));
                IM[j] = f2fma(P, sbi,  f2fma(Q, sbr, f2fma(Ro, sai,  f2mul(Io, sar))));
            }
        }
        if (d == 0) {
            int g0 = lane ^ (lane >> 1);
            float2 nR[4], nI[4];
            #pragma unroll
            for (int j = 0; j < 4; j++) {
                int sl = g0 ^ ((j & 1) << 4);
                int sA = j ^ (j >> 1), sB = sA ^ 2;
                nR[j].x = __shfl_sync(FULLMASK, RE[sA].x, sl);
                nR[j].y = __shfl_sync(FULLMASK, RE[sB].y, sl);
                nI[j].x = __shfl_sync(FULLMASK, IM[sA].x, sl);
                nI[j].y = __shfl_sync(FULLMASK, IM[sB].y, sl);
            }
            #pragma unroll
            for (int j = 0; j < 4; j++) { RE[j] = nR[j]; IM[j] = nI[j]; }
        }
    }

    float px[4], py[4];
    #pragma unroll
    for (int j = 0; j < 4; j++) {
        float2 p2 = f2fma(IM[j], IM[j], f2mul(RE[j], RE[j]));
        px[j] = p2.x; py[j] = p2.y;
    }
    float C = (px[0] + px[1] + px[2] + px[3]) - (py[0] + py[1] + py[2] + py[3]);
    float B = (px[0] + px[1] - px[2] - px[3]) - (py[0] + py[1] - py[2] - py[3]);
    float A = (px[0] - px[1] - px[2] + px[3]) - (py[0] - py[1] - py[2] + py[3]);
    float v[8];
    v[0] = C;
    v[1] = B;
    v[2] = A;
    v[3] = (lane & 16)              ? -A : A;
    v[4] = (__popc(lane >> 3) & 1)  ? -A : A;
    v[5] = (__popc(lane >> 2) & 1)  ? -A : A;
    v[6] = (__popc(lane >> 1) & 1)  ? -A : A;
    v[7] = (__popc(lane) & 1)       ? -A : A;
    #pragma unroll
    for (int off = 16; off; off >>= 1) {
        #pragma unroll
        for (int q = 0; q < 8; q++)
            v[q] += __shfl_xor_sync(FULLMASK, v[q], off);
    }
    #pragma unroll
    for (int q = 0; q < 8; q++) ang[q] = v[q];
}

__device__ __forceinline__ float fast_sigmoid(float x) { return 1.f / (1.f + __expf(-x)); }
__device__ __forceinline__ float fast_tanh(float x)    { return 2.f / (1.f + __expf(-2.f * x)) - 1.f; }

// ---------------------------------------------------------------------------
// Kernel 3: persistent recurrent kernel. One CTA per batch element, 8 warps.
// ---------------------------------------------------------------------------
__global__ __launch_bounds__(256, 1)
void qlstm_main(const float* __restrict__ W_q2h,
                const float* __restrict__ fpar, const float* __restrict__ ipar,
                const float* __restrict__ gpar, const float* __restrict__ opar,
                float* __restrict__ out) {
    __shared__ float wq[NH * 9];
    __shared__ __align__(16) float Usm[8 * 384];
    __shared__ __align__(16) float hx[NH];
    __shared__ float xsq[NT * 8];
    __shared__ float qs[8];
    __shared__ float ybuf[32];

    int tid = threadIdx.x, lane = tid & 31, wid = tid >> 5;
    int bb = blockIdx.x;

    float mreg[16];
    #pragma unroll
    for (int i = 0; i < 16; i++) mreg[i] = g_M[wid * 1024 + 512 + lane + 32 * i];

    for (int idx = tid; idx < NH * 8; idx += 256)
        wq[(idx >> 3) * 9 + (idx & 7)] = W_q2h[idx];
    for (int idx = tid; idx < 512; idx += 256) hx[idx] = 0.f;
    xsq[tid] = g_qinx[((tid >> 3) * NB + bb) * 8 + (tid & 7)];

    if (tid < 128) {
        int q = tid & 7, d = (tid >> 3) & 1, gc = (tid >> 4) & 1, gi = tid >> 5;
        const float* P = (gi == 0) ? fpar : (gi == 1) ? ipar : (gi == 2) ? gpar : opar;
        const float* pp = P + ((gc * 2 + d) * 8 + q) * 3;
        float a = 0.5f * pp[0], b = 0.5f * pp[1], c = 0.5f * pp[2];
        float ca = cosf(a), sa = sinf(a);
        float cb = cosf(b), sb = sinf(b);
        float cc = cosf(c), sc = sinf(c);
        float m00r =  ca * cb, m00i = -ca * sb;
        float m01r = -sa * cb, m01i =  sa * sb;
        float m10r =  sa * cb, m10i =  sa * sb;
        float m11r =  ca * cb, m11i =  ca * sb;
        float u00r =  cc * m00r + sc * m10i, u00i =  cc * m00i - sc * m10r;
        float u01r =  cc * m01r + sc * m11i, u01i =  cc * m01i - sc * m11r;
        float u10r =  sc * m00i + cc * m10r, u10i = -sc * m00r + cc * m10i;
        float u11r =  sc * m01i + cc * m11r, u11i = -sc * m01r + cc * m11i;

        float* L = Usm + ((gi * 2 + gc) * 2 + d) * 192 + q * 24;
        if (q == 0) {
            L[0]  = u00r;  L[1]  = u11r;
            L[2]  = u00i;  L[3]  = u11i;
            L[4]  = -u00i; L[5]  = -u11i;
            L[6]  = u01r;  L[7]  = u10r;
            L[8]  = u01i;  L[9]  = u10i;
            L[10] = -u01i; L[11] = -u10i;
        } else if (q < 3) {
            L[0]=u00r;  L[1]=u00r;   L[2]=u00i;  L[3]=u00i;   L[4]=-u00i; L[5]=-u00i;
            L[6]=u01r;  L[7]=u01r;   L[8]=u01i;  L[9]=u01i;   L[10]=-u01i;L[11]=-u01i;
            L[12]=u10r; L[13]=u10r;  L[14]=u10i; L[15]=u10i;  L[16]=-u10i;L[17]=-u10i;
            L[18]=u11r; L[19]=u11r;  L[20]=u11i; L[21]=u11i;  L[22]=-u11i;L[23]=-u11i;
        } else {
            L[0]=u00r;  L[1]=u00r;   L[2]=u00i;  L[3]=u00i;   L[4]=-u00i; L[5]=-u00i;
            L[6]=u01r;  L[7]=u01r;   L[8]=u01i;  L[9]=u01i;   L[10]=-u01i;L[11]=-u01i;
            L[12]=u11r; L[13]=u11r;  L[14]=u11i; L[15]=u11i;  L[16]=-u11i;L[17]=-u11i;
            L[18]=u10r; L[19]=u10r;  L[20]=u10i; L[21]=u10i;  L[22]=-u10i;L[23]=-u10i;
        }
    }
    float cx0 = 0.f, cx1 = 0.f;
    __syncthreads();

    #pragma unroll 1
    for (int t = 0; t < NT; t++) {
        // --- qin dot: warp w computes hx . Mh[w] ---
        {
            float acc = 0.f;
            #pragma unroll
            for (int i = 0; i < 16; i++)
                acc = fmaf(hx[lane + 32 * i], mreg[i], acc);
            #pragma unroll
            for (int off = 16; off; off >>= 1)
                acc += __shfl_xor_sync(FULLMASK, acc, off);
            if (lane == 0) qs[wid] = acc;
        }
        __syncthreads();

        // --- quantum gates: warp w = gate w ---
        if (wid < 4) {
            float ang[8];
            #pragma unroll
            for (int j = 0; j < 8; j++) ang[j] = qs[j] + xsq[t * 8 + j];

            #pragma unroll 1
            for (int gc = 0; gc < 2; gc++)
                run_circuit(Usm + (wid * 2 + gc) * 384, ang, lane);

            if (lane == 0) {
                #pragma unroll
                for (int j = 0; j < 8; j++) ybuf[wid * 8 + j] = ang[j];
            }
        }
        __syncthreads();

        // --- output stage: y @ W_q2h.T, activations, LSTM cell update ---
        #pragma unroll
        for (int u = 0; u < 2; u++) {
            int h = tid + u * 256;
            float af = 0.f, aiv = 0.f, agv = 0.f, aov = 0.f;
            #pragma unroll
            for (int j = 0; j < 8; j++) {
                float w = wq[h * 9 + j];
                af  = fmaf(ybuf[j],      w, af);
                aiv = fmaf(ybuf[8 + j],  w, aiv);
                agv = fmaf(ybuf[16 + j], w, agv);
                aov = fmaf(ybuf[24 + j], w, aov);
            }
            float fv = fast_sigmoid(af);
            float iv = fast_sigmoid(aiv);
            float gv = fast_tanh(agv);
            float ov = fast_sigmoid(aov);
            float cprev = u ? cx1 : cx0;
            float cn = fv * cprev + iv * gv;
            if (u) cx1 = cn; else cx0 = cn;
            float hn = ov * fast_tanh(cn);
            hx[h] = hn;
            out[(t * NB + bb) * NH + h] = hn;
        }
        __syncthreads();
    }

    #pragma unroll
    for (int u = 0; u < 2; u++) {
        int h = tid + u * 256;
        out[NT * NB * NH + bb * NH + h]           = hx[h];
        out[NT * NB * NH + NB * NH + bb * NH + h] = (u ? cx1 : cx0);
    }
}

// ---------------------------------------------------------------------------
extern "C" void kernel_launch(void* const* d_in, const int* in_sizes, int n_in,
                              void* d_out, int out_size) {
    const float* inputs = (const float*)d_in[0];
    const float* W_proj = (const float*)d_in[1];
    const float* b_proj = (const float*)d_in[2];
    const float* W_toq  = (const float*)d_in[3];
    const float* W_q2h  = (const float*)d_in[4];
    const float* fp     = (const float*)d_in[5];
    const float* ip     = (const float*)d_in[6];
    const float* gp     = (const float*)d_in[7];
    const float* op     = (const float*)d_in[8];
    float* out = (float*)d_out;

    mprep_kernel<<<dim3(8, 4, 1), 256>>>(W_proj, W_toq, b_proj);
    qinx_kernel<<<128, 256>>>(inputs);
    qlstm_main<<<NB, 256>>>(W_q2h, fp, ip, gp, op, out);
}